// round 1
// baseline (speedup 1.0000x reference)
#include <cuda_runtime.h>
#include <math.h>

// Problem constants
#define BSZ   2
#define SEQ   2048
#define EMB   2048
#define NH    16
#define DH    128
#define QKVN  ((NH + 2) * DH)   // 2304

// Scratch (allocation-free rule: __device__ globals)
__device__ float g_qkv[(size_t)BSZ * SEQ * QKVN];    // [B*S, 2304]
__device__ float g_attn[(size_t)BSZ * SEQ * EMB];    // [B*S, 2048]

// ---------------------------------------------------------------------------
// Generic fp32 GEMM: C[M,N] = A[M,K] @ B[K,N], all row-major.
// 128x128 block, KTILE=8, 256 threads, 8x8 per-thread fragments.
// B-fragment split into cols [tx*4, tx*4+4) and [64+tx*4, 64+tx*4+4) so the
// LDS.128 fragment loads are bank-conflict free.
// Requires M,N,K multiples of 128/8 (true for all three uses).
// ---------------------------------------------------------------------------
__global__ void __launch_bounds__(256) gemm128(const float* __restrict__ A,
                                               const float* __restrict__ Bm,
                                               float* __restrict__ C,
                                               int M, int N, int K) {
    __shared__ float As[8][132];   // [kk][m], padded: conflict-free transpose stores
    __shared__ float Bs[8][128];   // [kk][n]

    const int t  = threadIdx.x;
    const int bm = blockIdx.y * 128;
    const int bn = blockIdx.x * 128;
    const int ty = t >> 4;         // 0..15 -> rows ty*8..+8
    const int tx = t & 15;         // 0..15 -> cols tx*4 and 64+tx*4

    const int arow = t >> 1;            // 0..127
    const int ak   = (t & 1) << 2;      // 0 or 4
    const int brow = t >> 5;            // 0..7
    const int bcol = (t & 31) << 2;     // 0..124

    const float* Ap = A + (size_t)(bm + arow) * K + ak;
    const float* Bp = Bm + (size_t)brow * N + bn + bcol;

    float acc[8][8];
#pragma unroll
    for (int i = 0; i < 8; i++)
#pragma unroll
        for (int j = 0; j < 8; j++) acc[i][j] = 0.0f;

    for (int k0 = 0; k0 < K; k0 += 8) {
        // prefetch into registers before the barrier (overlaps prior compute)
        float4 av = *(const float4*)(Ap + k0);
        float4 bv = *(const float4*)(Bp + (size_t)k0 * N);
        __syncthreads();
        As[ak + 0][arow] = av.x;
        As[ak + 1][arow] = av.y;
        As[ak + 2][arow] = av.z;
        As[ak + 3][arow] = av.w;
        *(float4*)&Bs[brow][bcol] = bv;
        __syncthreads();

#pragma unroll
        for (int kk = 0; kk < 8; kk++) {
            float4 a0 = *(const float4*)&As[kk][ty * 8];
            float4 a1 = *(const float4*)&As[kk][ty * 8 + 4];
            float4 b0 = *(const float4*)&Bs[kk][tx * 4];
            float4 b1 = *(const float4*)&Bs[kk][64 + tx * 4];
            float a[8] = {a0.x, a0.y, a0.z, a0.w, a1.x, a1.y, a1.z, a1.w};
            float b[8] = {b0.x, b0.y, b0.z, b0.w, b1.x, b1.y, b1.z, b1.w};
#pragma unroll
            for (int i = 0; i < 8; i++)
#pragma unroll
                for (int j = 0; j < 8; j++) acc[i][j] += a[i] * b[j];
        }
    }

#pragma unroll
    for (int i = 0; i < 8; i++) {
        float* Cr = C + (size_t)(bm + ty * 8 + i) * N + bn;
        float4 c0 = make_float4(acc[i][0], acc[i][1], acc[i][2], acc[i][3]);
        float4 c1 = make_float4(acc[i][4], acc[i][5], acc[i][6], acc[i][7]);
        *(float4*)(Cr + tx * 4)      = c0;
        *(float4*)(Cr + 64 + tx * 4) = c1;
    }
}

// ---------------------------------------------------------------------------
// Flash-attention MQA kernel.
// Grid: (S/64, H, B). Block: 256 threads as 16x16.
// Each block: 64 queries of head h, streams over all 2048 keys in 64-wide tiles.
// Thread (ty,tx): score frag 4 queries (ty*4..) x 4 keys (tx*4..),
//                 O frag 4 queries x 8 cols (tx*4.. and 64+tx*4..).
// K tile is XOR-swizzled by ((row>>2)&7)<<2 so fragment reads (rows stride
// 4*128 words across lanes) are conflict-free.
// ---------------------------------------------------------------------------
__global__ void __launch_bounds__(256) mqa_flash(const float* __restrict__ qkv,
                                                 float* __restrict__ attn) {
    extern __shared__ float sm[];
    float* Qs = sm;                 // [64][128], pre-scaled by 1/sqrt(D)
    float* Ks = sm + 64 * 128;      // [64][128], swizzled
    float* Vs = sm + 2 * 64 * 128;  // [64][128]
    float* Ps = sm + 3 * 64 * 128;  // [64][64]

    const int t  = threadIdx.x;
    const int ty = t >> 4, tx = t & 15;
    const int q0 = blockIdx.x * 64;
    const int h  = blockIdx.y;
    const int b  = blockIdx.z;
    const int qy = ty * 4;
    const int kx = tx * 4;
    const float scale = rsqrtf((float)DH);

    // tile-load mapping: 8 float4 per thread; row = c*8 + t/32, d4 = (t%32)*4
    const int lrow = t >> 5;
    const int ld4  = (t & 31) << 2;

    // ---- load Q tile (once), fold in softmax scale ----
#pragma unroll
    for (int c = 0; c < 8; c++) {
        int row = c * 8 + lrow;
        float4 v = *(const float4*)(qkv + (size_t)(b * SEQ + q0 + row) * QKVN + h * DH + ld4);
        v.x *= scale; v.y *= scale; v.z *= scale; v.w *= scale;
        *(float4*)&Qs[row * 128 + ld4] = v;
    }

    float m_[4], l_[4], O[4][8];
#pragma unroll
    for (int i = 0; i < 4; i++) {
        m_[i] = -1e30f; l_[i] = 0.0f;
#pragma unroll
        for (int j = 0; j < 8; j++) O[i][j] = 0.0f;
    }

    const int swz = (tx & 7) << 2;   // matches store swizzle for rows kx..kx+3

    for (int t0 = 0; t0 < SEQ; t0 += 64) {
        __syncthreads();   // previous tile's PV reads done
        // ---- load K,V tiles (MQA: shared across heads; L2-resident) ----
#pragma unroll
        for (int c = 0; c < 8; c++) {
            int row = c * 8 + lrow;
            const float* base = qkv + (size_t)(b * SEQ + t0 + row) * QKVN;
            float4 kv = *(const float4*)(base + EMB + ld4);
            float4 vv = *(const float4*)(base + EMB + DH + ld4);
            int ks = ((row >> 2) & 7) << 2;
            *(float4*)&Ks[row * 128 + (ld4 ^ ks)] = kv;
            *(float4*)&Vs[row * 128 + ld4]        = vv;
        }
        __syncthreads();

        // ---- scores: s[i][j] = Q[qy+i] . K[kx+j]  (scale folded into Q) ----
        float s[4][4];
#pragma unroll
        for (int i = 0; i < 4; i++)
#pragma unroll
            for (int j = 0; j < 4; j++) s[i][j] = 0.0f;

#pragma unroll 8
        for (int d = 0; d < 128; d += 4) {
            float4 qv[4], kv[4];
#pragma unroll
            for (int i = 0; i < 4; i++)
                qv[i] = *(const float4*)&Qs[(qy + i) * 128 + d];
#pragma unroll
            for (int j = 0; j < 4; j++)
                kv[j] = *(const float4*)&Ks[(kx + j) * 128 + (d ^ swz)];
#pragma unroll
            for (int i = 0; i < 4; i++)
#pragma unroll
                for (int j = 0; j < 4; j++)
                    s[i][j] += qv[i].x * kv[j].x + qv[i].y * kv[j].y +
                               qv[i].z * kv[j].z + qv[i].w * kv[j].w;
        }

        // ---- streaming softmax update (row reduce across 16 tx lanes) ----
#pragma unroll
        for (int i = 0; i < 4; i++) {
            float mt = fmaxf(fmaxf(s[i][0], s[i][1]), fmaxf(s[i][2], s[i][3]));
#pragma unroll
            for (int off = 8; off > 0; off >>= 1)
                mt = fmaxf(mt, __shfl_xor_sync(0xffffffffu, mt, off, 16));
            float mn = fmaxf(m_[i], mt);
            float corr = __expf(m_[i] - mn);
            float4 p;
            p.x = __expf(s[i][0] - mn);
            p.y = __expf(s[i][1] - mn);
            p.z = __expf(s[i][2] - mn);
            p.w = __expf(s[i][3] - mn);
            float rs = p.x + p.y + p.z + p.w;
#pragma unroll
            for (int off = 8; off > 0; off >>= 1)
                rs += __shfl_xor_sync(0xffffffffu, rs, off, 16);
            l_[i] = l_[i] * corr + rs;
            m_[i] = mn;
#pragma unroll
            for (int j = 0; j < 8; j++) O[i][j] *= corr;
            *(float4*)&Ps[(qy + i) * 64 + kx] = p;
        }
        __syncthreads();

        // ---- O += P @ V ----
#pragma unroll 4
        for (int kk = 0; kk < 64; kk += 4) {
            float parr[4][4];
#pragma unroll
            for (int i = 0; i < 4; i++) {
                float4 pv = *(const float4*)&Ps[(qy + i) * 64 + kk];
                parr[i][0] = pv.x; parr[i][1] = pv.y;
                parr[i][2] = pv.z; parr[i][3] = pv.w;
            }
#pragma unroll
            for (int u = 0; u < 4; u++) {
                float4 v1 = *(const float4*)&Vs[(kk + u) * 128 + tx * 4];
                float4 v2 = *(const float4*)&Vs[(kk + u) * 128 + 64 + tx * 4];
#pragma unroll
                for (int i = 0; i < 4; i++) {
                    float pu = parr[i][u];
                    O[i][0] += pu * v1.x; O[i][1] += pu * v1.y;
                    O[i][2] += pu * v1.z; O[i][3] += pu * v1.w;
                    O[i][4] += pu * v2.x; O[i][5] += pu * v2.y;
                    O[i][6] += pu * v2.z; O[i][7] += pu * v2.w;
                }
            }
        }
    }

    // ---- epilogue: normalize, write attn[b, q, h*128 + c] ----
#pragma unroll
    for (int i = 0; i < 4; i++) {
        float inv = 1.0f / l_[i];
        float* Ar = attn + (size_t)(b * SEQ + q0 + qy + i) * EMB + h * DH;
        float4 o0 = make_float4(O[i][0] * inv, O[i][1] * inv, O[i][2] * inv, O[i][3] * inv);
        float4 o1 = make_float4(O[i][4] * inv, O[i][5] * inv, O[i][6] * inv, O[i][7] * inv);
        *(float4*)(Ar + tx * 4)      = o0;
        *(float4*)(Ar + 64 + tx * 4) = o1;
    }
}

// ---------------------------------------------------------------------------
extern "C" void kernel_launch(void* const* d_in, const int* in_sizes, int n_in,
                              void* d_out, int out_size) {
    const float* x      = (const float*)d_in[0];   // [B,S,E]
    const float* w_attn = (const float*)d_in[1];   // [E, 2304]
    const float* w_out  = (const float*)d_in[2];   // [E, E]
    float* out = (float*)d_out;                    // [B,S,E]

    float* qkv  = nullptr;
    float* attn = nullptr;
    cudaGetSymbolAddress((void**)&qkv,  g_qkv);
    cudaGetSymbolAddress((void**)&attn, g_attn);

    const int flash_smem = (3 * 64 * 128 + 64 * 64) * (int)sizeof(float);  // 112 KB
    cudaFuncSetAttribute(mqa_flash, cudaFuncAttributeMaxDynamicSharedMemorySize,
                         flash_smem);

    dim3 blk(256);
    const int M = BSZ * SEQ;  // 4096

    // 1) qkv = x @ w_attn   : [4096,2048]x[2048,2304]
    gemm128<<<dim3(QKVN / 128, M / 128), blk>>>(x, w_attn, qkv, M, QKVN, EMB);

    // 2) flash MQA attention -> g_attn [B,S,E]
    mqa_flash<<<dim3(SEQ / 64, NH, BSZ), blk, flash_smem>>>(qkv, attn);

    // 3) out = attn @ w_out : [4096,2048]x[2048,2048]
    gemm128<<<dim3(EMB / 128, M / 128), blk>>>(attn, w_out, out, M, EMB, EMB);
}